// round 1
// baseline (speedup 1.0000x reference)
#include <cuda_runtime.h>
#include <cuda_bf16.h>

#define B_   256
#define N_   64
#define K_   12
#define D_   128
#define ROWS (B_ * N_)          // 16384
#define NBLK 444                // 3 * 148 SMs
#define WPB  4                  // warps per block
#define SMEM_BYTES ((16384 + WPB * 128) * 4)   // Wv (64KB) + w staging

// Precomputed: uq = Wq @ wa_q, uk = Wk @ wa_k, c = bq.wa_q + bk.wa_k + ba
__device__ float g_uq[D_];
__device__ float g_uk[D_];
__device__ float g_c;

__global__ void gat_prologue(const float* __restrict__ Wq, const float* __restrict__ bq,
                             const float* __restrict__ Wk, const float* __restrict__ bk,
                             const float* __restrict__ waq, const float* __restrict__ wak,
                             const float* __restrict__ ba) {
    const int i = threadIdx.x;   // 128 threads
    float sq = 0.f, sk = 0.f;
    const float4* wq4 = (const float4*)(Wq + i * D_);
    const float4* wk4 = (const float4*)(Wk + i * D_);
    const float4* aq4 = (const float4*)waq;
    const float4* ak4 = (const float4*)wak;
#pragma unroll
    for (int j = 0; j < D_ / 4; ++j) {
        float4 a = wq4[j], b = aq4[j];
        sq = fmaf(a.x, b.x, fmaf(a.y, b.y, fmaf(a.z, b.z, fmaf(a.w, b.w, sq))));
        float4 c = wk4[j], d = ak4[j];
        sk = fmaf(c.x, d.x, fmaf(c.y, d.y, fmaf(c.z, d.z, fmaf(c.w, d.w, sk))));
    }
    g_uq[i] = sq;
    g_uk[i] = sk;

    __shared__ float red[D_];
    red[i] = bq[i] * waq[i] + bk[i] * wak[i];
    __syncthreads();
#pragma unroll
    for (int s = 64; s > 0; s >>= 1) {
        if (i < s) red[i] += red[i + s];
        __syncthreads();
    }
    if (i == 0) g_c = red[0] + ba[0];
}

__device__ __forceinline__ float dot4(float4 a, float4 b) {
    return fmaf(a.x, b.x, fmaf(a.y, b.y, fmaf(a.z, b.z, a.w * b.w)));
}

__global__ __launch_bounds__(128, 3)
void gat_main(const float* __restrict__ nodes, const float* __restrict__ nbrs,
              const float* __restrict__ mask, const float* __restrict__ Wv,
              const float* __restrict__ bv, float* __restrict__ out) {
    extern __shared__ float sm[];
    float* wv_s  = sm;              // [128][128] row-major
    float* stage = sm + 16384;      // per-warp w vectors [WPB][128]

    const int tid = threadIdx.x;
    const int wid = tid >> 5;
    const int l   = tid & 31;

    // Cooperative load of Wv into shared (amortized over ~37 rows per block)
    const float4* wv4 = (const float4*)Wv;
    float4* wvs4 = (float4*)wv_s;
#pragma unroll
    for (int i = tid; i < 16384 / 4; i += 128) wvs4[i] = wv4[i];
    __syncthreads();

    const float4 uq4 = ((const float4*)g_uq)[l];
    const float4 uk4 = ((const float4*)g_uk)[l];
    const float  cc  = g_c;
    const float4 bv4 = ((const float4*)bv)[l];   // lane l outputs cols 4l..4l+3

    float* wsh = stage + wid * 128;
    const int gw = blockIdx.x * WPB + wid;

    for (int row = gw; row < ROWS; row += NBLK * WPB) {
        // ---- load node + 12 neighbors (lane l holds elements 4l..4l+3) ----
        float4 nh0 = ((const float4*)(nodes + row * D_))[l];
        const float4* np = (const float4*)(nbrs + (long)row * (K_ * D_));
        float4 nhj[K_];
        float  kd[K_ + 1];
        float  qd = dot4(nh0, uq4);
        kd[0] = dot4(nh0, uk4);
#pragma unroll
        for (int j = 0; j < K_; ++j) {
            float4 v = np[j * 32 + l];
            nhj[j] = v;
            kd[j + 1] = dot4(v, uk4);
        }

        // ---- butterfly reduce 14 dot products across the warp ----
#pragma unroll
        for (int off = 16; off; off >>= 1) {
            qd += __shfl_xor_sync(0xFFFFFFFFu, qd, off);
#pragma unroll
            for (int j = 0; j < K_ + 1; ++j)
                kd[j] += __shfl_xor_sync(0xFFFFFFFFu, kd[j], off);
        }

        // ---- masked LeakyReLU-exp softmax over 13 slots ----
        const float sbase = qd + cc;
        float e[K_ + 1];
        float s = 0.f;
#pragma unroll
        for (int j = 0; j < K_ + 1; ++j) {
            float t = kd[j] + sbase;
            t = (t >= 0.f) ? t : 0.2f * t;
            float ej = __expf(t);
            if (j > 0) ej *= mask[row * K_ + (j - 1)];
            e[j] = ej;
            s += ej;
        }
        const float inv  = 1.f / (s + 1e-16f);
        const float asum = s * inv;

        // ---- weighted combine: w = sum_j attn_j * nh_j ----
        float a0 = e[0] * inv;
        float4 w;
        w.x = a0 * nh0.x; w.y = a0 * nh0.y; w.z = a0 * nh0.z; w.w = a0 * nh0.w;
#pragma unroll
        for (int j = 0; j < K_; ++j) {
            float a = e[j + 1] * inv;
            w.x = fmaf(a, nhj[j].x, w.x);
            w.y = fmaf(a, nhj[j].y, w.y);
            w.z = fmaf(a, nhj[j].z, w.z);
            w.w = fmaf(a, nhj[j].w, w.w);
        }

        // ---- GEMV: out = w @ Wv + asum * bv ----
        __syncwarp();
        ((float4*)wsh)[l] = w;
        __syncwarp();

        float4 acc = make_float4(0.f, 0.f, 0.f, 0.f);
#pragma unroll
        for (int i0 = 0; i0 < D_; i0 += 4) {
            float4 w4 = ((const float4*)wsh)[i0 >> 2];
            float4 c0 = *(const float4*)(wv_s + (i0 + 0) * D_ + 4 * l);
            acc.x = fmaf(w4.x, c0.x, acc.x); acc.y = fmaf(w4.x, c0.y, acc.y);
            acc.z = fmaf(w4.x, c0.z, acc.z); acc.w = fmaf(w4.x, c0.w, acc.w);
            float4 c1 = *(const float4*)(wv_s + (i0 + 1) * D_ + 4 * l);
            acc.x = fmaf(w4.y, c1.x, acc.x); acc.y = fmaf(w4.y, c1.y, acc.y);
            acc.z = fmaf(w4.y, c1.z, acc.z); acc.w = fmaf(w4.y, c1.w, acc.w);
            float4 c2 = *(const float4*)(wv_s + (i0 + 2) * D_ + 4 * l);
            acc.x = fmaf(w4.z, c2.x, acc.x); acc.y = fmaf(w4.z, c2.y, acc.y);
            acc.z = fmaf(w4.z, c2.z, acc.z); acc.w = fmaf(w4.z, c2.w, acc.w);
            float4 c3 = *(const float4*)(wv_s + (i0 + 3) * D_ + 4 * l);
            acc.x = fmaf(w4.w, c3.x, acc.x); acc.y = fmaf(w4.w, c3.y, acc.y);
            acc.z = fmaf(w4.w, c3.z, acc.z); acc.w = fmaf(w4.w, c3.w, acc.w);
        }
        acc.x = fmaf(asum, bv4.x, acc.x);
        acc.y = fmaf(asum, bv4.y, acc.y);
        acc.z = fmaf(asum, bv4.z, acc.z);
        acc.w = fmaf(asum, bv4.w, acc.w);

        ((float4*)(out + (long)row * D_))[l] = acc;
        __syncwarp();   // wsh reused next iteration
    }
}

extern "C" void kernel_launch(void* const* d_in, const int* in_sizes, int n_in,
                              void* d_out, int out_size) {
    const float* nodes = (const float*)d_in[0];   // [B,N,D]
    const float* nbrs  = (const float*)d_in[1];   // [B,N,K,D]
    const float* mask  = (const float*)d_in[2];   // [B,N,K]
    const float* Wq    = (const float*)d_in[3];
    const float* bq    = (const float*)d_in[4];
    const float* Wk    = (const float*)d_in[5];
    const float* bk    = (const float*)d_in[6];
    const float* Wv    = (const float*)d_in[7];
    const float* bv    = (const float*)d_in[8];
    const float* waq   = (const float*)d_in[9];
    const float* wak   = (const float*)d_in[10];
    const float* ba    = (const float*)d_in[11];
    float* out = (float*)d_out;

    cudaFuncSetAttribute(gat_main, cudaFuncAttributeMaxDynamicSharedMemorySize, SMEM_BYTES);

    gat_prologue<<<1, 128>>>(Wq, bq, Wk, bk, waq, wak, ba);
    gat_main<<<NBLK, 128, SMEM_BYTES>>>(nodes, nbrs, mask, Wv, bv, out);
}

// round 2
// speedup vs baseline: 1.0717x; 1.0717x over previous
#include <cuda_runtime.h>

#define B_   256
#define N_   64
#define K_   12
#define D_   128
#define ROWS 16384
#define TILE_M 64
#define THREADS 128
#define NBLK (ROWS / TILE_M)    // 256 blocks

// shared floats: Wv[128*128] + As[64*128] + Ssum[64] + uq[128] + uk[128] + red[8]
#define SM_FLOATS (16384 + TILE_M * 128 + 64 + 128 + 128 + 8)

__device__ __forceinline__ float dot4(float4 a, float4 b) {
    return fmaf(a.x, b.x, fmaf(a.y, b.y, fmaf(a.z, b.z, a.w * b.w)));
}
__device__ __forceinline__ void ffma2(unsigned long long& d, unsigned long long a, unsigned long long b) {
    asm("fma.rn.f32x2 %0, %1, %2, %0;" : "+l"(d) : "l"(a), "l"(b));
}
__device__ __forceinline__ unsigned long long pack2(float x) {
    unsigned long long r;
    asm("mov.b64 %0, {%1, %1};" : "=l"(r) : "f"(x));
    return r;
}
__device__ __forceinline__ float2 unpack2(unsigned long long v) {
    float2 f;
    asm("mov.b64 {%0, %1}, %2;" : "=f"(f.x), "=f"(f.y) : "l"(v));
    return f;
}

__global__ __launch_bounds__(THREADS, 2)
void gat_fused(const float* __restrict__ nodes, const float* __restrict__ nbrs,
               const float* __restrict__ mask,
               const float* __restrict__ Wq, const float* __restrict__ bq,
               const float* __restrict__ Wk, const float* __restrict__ bk,
               const float* __restrict__ Wv, const float* __restrict__ bv,
               const float* __restrict__ waq, const float* __restrict__ wak,
               const float* __restrict__ ba, float* __restrict__ out)
{
    extern __shared__ float sm[];
    float* wv_s = sm;                     // [128][128]
    float* As   = sm + 16384;             // [64][128]
    float* Ssum = As + TILE_M * 128;      // [64]
    float* uq_s = Ssum + 64;              // [128]
    float* uk_s = uq_s + 128;             // [128]
    float* red  = uk_s + 128;             // [8]

    const int tid = threadIdx.x;
    const int wid = tid >> 5;
    const int l   = tid & 31;

    // ---- Wv -> shared (cooperative) ----
    {
        const float4* src = (const float4*)Wv;
        float4* dst = (float4*)wv_s;
#pragma unroll
        for (int i = tid; i < 16384 / 4; i += THREADS) dst[i] = src[i];
    }

    // ---- fold in the prologue: uq = Wq@waq, uk = Wk@wak, c = bq.waq+bk.wak+ba ----
    {
        float sq = 0.f, sk = 0.f;
        const float4* wq4 = (const float4*)(Wq + tid * D_);
        const float4* wk4 = (const float4*)(Wk + tid * D_);
        const float4* aq4 = (const float4*)waq;
        const float4* ak4 = (const float4*)wak;
#pragma unroll
        for (int j = 0; j < D_ / 4; ++j) {
            float4 a = wq4[j], b = aq4[j];
            sq = fmaf(a.x, b.x, fmaf(a.y, b.y, fmaf(a.z, b.z, fmaf(a.w, b.w, sq))));
            float4 c2 = wk4[j], d2 = ak4[j];
            sk = fmaf(c2.x, d2.x, fmaf(c2.y, d2.y, fmaf(c2.z, d2.z, fmaf(c2.w, d2.w, sk))));
        }
        uq_s[tid] = sq;
        uk_s[tid] = sk;
        float p = bq[tid] * waq[tid] + bk[tid] * wak[tid];
#pragma unroll
        for (int off = 16; off; off >>= 1) p += __shfl_xor_sync(0xFFFFFFFFu, p, off);
        if (l == 0) red[wid] = p;
    }
    __syncthreads();

    const float cc = red[0] + red[1] + red[2] + red[3] + __ldg(ba);
    const float4 uq4 = ((const float4*)uq_s)[l];
    const float4 uk4 = ((const float4*)uk_s)[l];

    const int row0 = blockIdx.x * TILE_M;

    // ================= phase 1: attention + weighted combine =================
    // warp w handles tile rows [w*16, w*16+16)
#pragma unroll 1
    for (int i = 0; i < TILE_M / 4 / 8; ++i) { }  // (placeholder removed by compiler)
    for (int i = 0; i < 16; ++i) {
        const int r   = wid * 16 + i;
        const int row = row0 + r;

        float4 nh0 = __ldg((const float4*)(nodes + (size_t)row * D_) + l);
        const float4* np = (const float4*)(nbrs + (size_t)row * (K_ * D_));
        float4 nhj[K_];
        float  kd[K_ + 1];
        float  qd = dot4(nh0, uq4);
        kd[0] = dot4(nh0, uk4);
#pragma unroll
        for (int j = 0; j < K_; ++j) {
            float4 v = __ldg(np + j * 32 + l);
            nhj[j] = v;
            kd[j + 1] = dot4(v, uk4);
        }

#pragma unroll
        for (int off = 16; off; off >>= 1) {
            qd += __shfl_xor_sync(0xFFFFFFFFu, qd, off);
#pragma unroll
            for (int j = 0; j <= K_; ++j)
                kd[j] += __shfl_xor_sync(0xFFFFFFFFu, kd[j], off);
        }

        const float sbase = qd + cc;
        float e[K_ + 1];
        float s = 0.f;
#pragma unroll
        for (int j = 0; j <= K_; ++j) {
            float t = kd[j] + sbase;
            t = (t >= 0.f) ? t : 0.2f * t;
            float ej = __expf(t);
            if (j) ej *= __ldg(mask + (size_t)row * K_ + (j - 1));
            e[j] = ej;
            s += ej;
        }
        const float inv = 1.f / (s + 1e-16f);

        float a0 = e[0] * inv;
        float4 w = make_float4(a0 * nh0.x, a0 * nh0.y, a0 * nh0.z, a0 * nh0.w);
#pragma unroll
        for (int j = 0; j < K_; ++j) {
            float a = e[j + 1] * inv;
            w.x = fmaf(a, nhj[j].x, w.x);
            w.y = fmaf(a, nhj[j].y, w.y);
            w.z = fmaf(a, nhj[j].z, w.z);
            w.w = fmaf(a, nhj[j].w, w.w);
        }

        ((float4*)(As + r * 128))[l] = w;
        if (l == 0) Ssum[r] = s * inv;
    }
    __syncthreads();

    // ================= phase 2: [64,128] x Wv[128,128] register-tiled GEMM ====
    // thread tile: 8 rows x 8 cols; m_id = tid>>4 (0..7), n_id = tid&15 (0..15)
    const int m_id = tid >> 4;
    const int n_id = tid & 15;
    const float* a_base = As + m_id * 8 * 128;
    const float* b_base = wv_s + n_id * 8;

    unsigned long long acc[8][4];
#pragma unroll
    for (int r = 0; r < 8; ++r)
#pragma unroll
        for (int c = 0; c < 4; ++c) acc[r][c] = 0ull;

#pragma unroll 2
    for (int k = 0; k < 128; k += 4) {
        float4 a4[8];
#pragma unroll
        for (int r = 0; r < 8; ++r)
            a4[r] = *(const float4*)(a_base + r * 128 + k);
#pragma unroll
        for (int kk = 0; kk < 4; ++kk) {
            const float* bp = b_base + (k + kk) * 128;
            ulonglong2 b01 = *(const ulonglong2*)bp;
            ulonglong2 b23 = *(const ulonglong2*)(bp + 4);
#pragma unroll
            for (int r = 0; r < 8; ++r) {
                float av = (kk == 0) ? a4[r].x : (kk == 1) ? a4[r].y
                         : (kk == 2) ? a4[r].z : a4[r].w;
                unsigned long long ap = pack2(av);
                ffma2(acc[r][0], ap, b01.x);
                ffma2(acc[r][1], ap, b01.y);
                ffma2(acc[r][2], ap, b23.x);
                ffma2(acc[r][3], ap, b23.y);
            }
        }
    }

    // ---- epilogue: + asum * bv, store ----
    const float* bvp = bv + n_id * 8;
    float4 bva = __ldg((const float4*)bvp);
    float4 bvb = __ldg((const float4*)bvp + 1);
#pragma unroll
    for (int r = 0; r < 8; ++r) {
        float srow = Ssum[m_id * 8 + r];
        float2 p0 = unpack2(acc[r][0]);
        float2 p1 = unpack2(acc[r][1]);
        float2 p2 = unpack2(acc[r][2]);
        float2 p3 = unpack2(acc[r][3]);
        float4 o0 = make_float4(fmaf(srow, bva.x, p0.x), fmaf(srow, bva.y, p0.y),
                                fmaf(srow, bva.z, p1.x), fmaf(srow, bva.w, p1.y));
        float4 o1 = make_float4(fmaf(srow, bvb.x, p2.x), fmaf(srow, bvb.y, p2.y),
                                fmaf(srow, bvb.z, p3.x), fmaf(srow, bvb.w, p3.y));
        float* op = out + (size_t)(row0 + m_id * 8 + r) * D_ + n_id * 8;
        *(float4*)op       = o0;
        *(float4*)(op + 4) = o1;
    }
}

extern "C" void kernel_launch(void* const* d_in, const int* in_sizes, int n_in,
                              void* d_out, int out_size) {
    const float* nodes = (const float*)d_in[0];
    const float* nbrs  = (const float*)d_in[1];
    const float* mask  = (const float*)d_in[2];
    const float* Wq    = (const float*)d_in[3];
    const float* bq    = (const float*)d_in[4];
    const float* Wk    = (const float*)d_in[5];
    const float* bk    = (const float*)d_in[6];
    const float* Wv    = (const float*)d_in[7];
    const float* bv    = (const float*)d_in[8];
    const float* waq   = (const float*)d_in[9];
    const float* wak   = (const float*)d_in[10];
    const float* ba    = (const float*)d_in[11];
    float* out = (float*)d_out;

    cudaFuncSetAttribute(gat_fused, cudaFuncAttributeMaxDynamicSharedMemorySize,
                         SM_FLOATS * 4);
    gat_fused<<<NBLK, THREADS, SM_FLOATS * 4>>>(nodes, nbrs, mask,
                                                Wq, bq, Wk, bk, Wv, bv,
                                                waq, wak, ba, out);
}

// round 3
// speedup vs baseline: 1.2790x; 1.1935x over previous
#include <cuda_runtime.h>

#define B_   256
#define N_   64
#define K_   12
#define D_   128
#define ROWS 16384

// ---------------- device scratch (allocation-free) ----------------
__device__ float g_uq[D_];
__device__ float g_uk[D_];
__device__ float g_c;
__device__ float g_As[(size_t)ROWS * D_];   // 8 MB combined vectors
__device__ float g_Ssum[ROWS];              // attention sums

__device__ __forceinline__ float dot4(float4 a, float4 b) {
    return fmaf(a.x, b.x, fmaf(a.y, b.y, fmaf(a.z, b.z, a.w * b.w)));
}
__device__ __forceinline__ void ffma2(unsigned long long& d, unsigned long long a, unsigned long long b) {
    asm("fma.rn.f32x2 %0, %1, %2, %0;" : "+l"(d) : "l"(a), "l"(b));
}
__device__ __forceinline__ unsigned long long pack2(float x) {
    unsigned long long r;
    asm("mov.b64 %0, {%1, %1};" : "=l"(r) : "f"(x));
    return r;
}
__device__ __forceinline__ float2 unpack2(unsigned long long v) {
    float2 f;
    asm("mov.b64 {%0, %1}, %2;" : "=f"(f.x), "=f"(f.y) : "l"(v));
    return f;
}

// ---------------- prologue: uq = Wq@waq, uk = Wk@wak, c ----------------
__global__ void gat_prologue(const float* __restrict__ Wq, const float* __restrict__ bq,
                             const float* __restrict__ Wk, const float* __restrict__ bk,
                             const float* __restrict__ waq, const float* __restrict__ wak,
                             const float* __restrict__ ba) {
    const int i = threadIdx.x;   // 128 threads
    float sq = 0.f, sk = 0.f;
    const float4* wq4 = (const float4*)(Wq + i * D_);
    const float4* wk4 = (const float4*)(Wk + i * D_);
    const float4* aq4 = (const float4*)waq;
    const float4* ak4 = (const float4*)wak;
#pragma unroll
    for (int j = 0; j < D_ / 4; ++j) {
        float4 a = wq4[j], b = aq4[j];
        sq = fmaf(a.x, b.x, fmaf(a.y, b.y, fmaf(a.z, b.z, fmaf(a.w, b.w, sq))));
        float4 c2 = wk4[j], d2 = ak4[j];
        sk = fmaf(c2.x, d2.x, fmaf(c2.y, d2.y, fmaf(c2.z, d2.z, fmaf(c2.w, d2.w, sk))));
    }
    g_uq[i] = sq;
    g_uk[i] = sk;

    float p = bq[i] * waq[i] + bk[i] * wak[i];
#pragma unroll
    for (int off = 16; off; off >>= 1) p += __shfl_xor_sync(0xFFFFFFFFu, p, off);
    __shared__ float red[4];
    if ((i & 31) == 0) red[i >> 5] = p;
    __syncthreads();
    if (i == 0) g_c = red[0] + red[1] + red[2] + red[3] + ba[0];
}

// ---------------- kernel A: attention + weighted combine (streaming) ----------------
#define A_WARPS 8
__global__ __launch_bounds__(A_WARPS * 32, 2)
void gat_attn(const float* __restrict__ nodes, const float* __restrict__ nbrs,
              const float* __restrict__ mask)
{
    const int wid = threadIdx.x >> 5;
    const int l   = threadIdx.x & 31;
    const int row = blockIdx.x * A_WARPS + wid;

    const float4 uq4 = ((const float4*)g_uq)[l];
    const float4 uk4 = ((const float4*)g_uk)[l];
    const float  cc  = g_c;

    // ---- load node + 12 neighbors (lane l owns elements 4l..4l+3) ----
    float4 nh0 = __ldg((const float4*)(nodes + (size_t)row * D_) + l);
    const float4* np = (const float4*)(nbrs + (size_t)row * (K_ * D_));
    float4 nhj[K_];
    float  kd[K_ + 1];
    float  qd = dot4(nh0, uq4);
    kd[0] = dot4(nh0, uk4);
#pragma unroll
    for (int j = 0; j < K_; ++j) {
        float4 v = __ldg(np + j * 32 + l);
        nhj[j] = v;
        kd[j + 1] = dot4(v, uk4);
    }

    // ---- butterfly reduce 14 dots across the warp ----
#pragma unroll
    for (int off = 16; off; off >>= 1) {
        qd += __shfl_xor_sync(0xFFFFFFFFu, qd, off);
#pragma unroll
        for (int j = 0; j <= K_; ++j)
            kd[j] += __shfl_xor_sync(0xFFFFFFFFu, kd[j], off);
    }

    // ---- masked LeakyReLU-exp softmax ----
    const float sbase = qd + cc;
    float e[K_ + 1];
    float s = 0.f;
#pragma unroll
    for (int j = 0; j <= K_; ++j) {
        float t = kd[j] + sbase;
        t = (t >= 0.f) ? t : 0.2f * t;
        float ej = __expf(t);
        if (j) ej *= __ldg(mask + (size_t)row * K_ + (j - 1));
        e[j] = ej;
        s += ej;
    }
    const float inv = 1.f / (s + 1e-16f);

    // ---- weighted combine ----
    float a0 = e[0] * inv;
    float4 w = make_float4(a0 * nh0.x, a0 * nh0.y, a0 * nh0.z, a0 * nh0.w);
#pragma unroll
    for (int j = 0; j < K_; ++j) {
        float a = e[j + 1] * inv;
        w.x = fmaf(a, nhj[j].x, w.x);
        w.y = fmaf(a, nhj[j].y, w.y);
        w.z = fmaf(a, nhj[j].z, w.z);
        w.w = fmaf(a, nhj[j].w, w.w);
    }

    ((float4*)(g_As + (size_t)row * D_))[l] = w;
    if (l == 0) g_Ssum[row] = s * inv;
}

// ---------------- kernel B: [16384,128] x Wv[128,128] + asum*bv ----------------
#define TILE_M 64
#define B_THREADS 128
#define B_SM_FLOATS (16384 + TILE_M * 128 + 64)

__global__ __launch_bounds__(B_THREADS, 2)
void gat_gemm(const float* __restrict__ Wv, const float* __restrict__ bv,
              float* __restrict__ out)
{
    extern __shared__ float sm[];
    float* wv_s   = sm;                  // [128][128]
    float* as_s   = sm + 16384;          // [64][128]
    float* ssum_s = as_s + TILE_M * 128; // [64]

    const int tid  = threadIdx.x;
    const int row0 = blockIdx.x * TILE_M;

    // cooperative loads
    {
        const float4* src = (const float4*)Wv;
        float4* dst = (float4*)wv_s;
#pragma unroll
        for (int i = tid; i < 16384 / 4; i += B_THREADS) dst[i] = src[i];
        const float4* asrc = (const float4*)(g_As + (size_t)row0 * D_);
        float4* adst = (float4*)as_s;
#pragma unroll
        for (int i = tid; i < TILE_M * 128 / 4; i += B_THREADS) adst[i] = asrc[i];
        if (tid < TILE_M) ssum_s[tid] = g_Ssum[row0 + tid];
    }
    __syncthreads();

    // thread tile: 8 rows x 8 cols
    const int m_id = tid >> 4;   // 0..7
    const int n_id = tid & 15;   // 0..15
    const float* a_base = as_s + m_id * 8 * 128;
    const float* b_base = wv_s + n_id * 8;

    unsigned long long acc[8][4];
#pragma unroll
    for (int r = 0; r < 8; ++r)
#pragma unroll
        for (int c = 0; c < 4; ++c) acc[r][c] = 0ull;

#pragma unroll 2
    for (int k = 0; k < 128; k += 4) {
        float4 a4[8];
#pragma unroll
        for (int r = 0; r < 8; ++r)
            a4[r] = *(const float4*)(a_base + r * 128 + k);
#pragma unroll
        for (int kk = 0; kk < 4; ++kk) {
            const float* bp = b_base + (k + kk) * 128;
            ulonglong2 b01 = *(const ulonglong2*)bp;
            ulonglong2 b23 = *(const ulonglong2*)(bp + 4);
#pragma unroll
            for (int r = 0; r < 8; ++r) {
                float av = (kk == 0) ? a4[r].x : (kk == 1) ? a4[r].y
                         : (kk == 2) ? a4[r].z : a4[r].w;
                unsigned long long ap = pack2(av);
                ffma2(acc[r][0], ap, b01.x);
                ffma2(acc[r][1], ap, b01.y);
                ffma2(acc[r][2], ap, b23.x);
                ffma2(acc[r][3], ap, b23.y);
            }
        }
    }

    // epilogue: + asum * bv
    const float* bvp = bv + n_id * 8;
    float4 bva = __ldg((const float4*)bvp);
    float4 bvb = __ldg((const float4*)bvp + 1);
#pragma unroll
    for (int r = 0; r < 8; ++r) {
        float srow = ssum_s[m_id * 8 + r];
        float2 p0 = unpack2(acc[r][0]);
        float2 p1 = unpack2(acc[r][1]);
        float2 p2 = unpack2(acc[r][2]);
        float2 p3 = unpack2(acc[r][3]);
        float4 o0 = make_float4(fmaf(srow, bva.x, p0.x), fmaf(srow, bva.y, p0.y),
                                fmaf(srow, bva.z, p1.x), fmaf(srow, bva.w, p1.y));
        float4 o1 = make_float4(fmaf(srow, bvb.x, p2.x), fmaf(srow, bvb.y, p2.y),
                                fmaf(srow, bvb.z, p3.x), fmaf(srow, bvb.w, p3.y));
        float* op = out + (size_t)(row0 + m_id * 8 + r) * D_ + n_id * 8;
        *(float4*)op       = o0;
        *(float4*)(op + 4) = o1;
    }
}

extern "C" void kernel_launch(void* const* d_in, const int* in_sizes, int n_in,
                              void* d_out, int out_size) {
    const float* nodes = (const float*)d_in[0];
    const float* nbrs  = (const float*)d_in[1];
    const float* mask  = (const float*)d_in[2];
    const float* Wq    = (const float*)d_in[3];
    const float* bq    = (const float*)d_in[4];
    const float* Wk    = (const float*)d_in[5];
    const float* bk    = (const float*)d_in[6];
    const float* Wv    = (const float*)d_in[7];
    const float* bv    = (const float*)d_in[8];
    const float* waq   = (const float*)d_in[9];
    const float* wak   = (const float*)d_in[10];
    const float* ba    = (const float*)d_in[11];
    float* out = (float*)d_out;

    cudaFuncSetAttribute(gat_gemm, cudaFuncAttributeMaxDynamicSharedMemorySize,
                         B_SM_FLOATS * 4);

    gat_prologue<<<1, 128>>>(Wq, bq, Wk, bk, waq, wak, ba);
    gat_attn<<<ROWS / A_WARPS, A_WARPS * 32>>>(nodes, nbrs, mask);
    gat_gemm<<<ROWS / TILE_M, B_THREADS, B_SM_FLOATS * 4>>>(Wv, bv, out);
}